// round 6
// baseline (speedup 1.0000x reference)
#include <cuda_runtime.h>
#include <cuda_bf16.h>
#include <cuda_fp16.h>
#include <cstdint>
#include <cstddef>

#define DEV __device__ __forceinline__

static constexpr int Bdim = 4096;
static constexpr int Ddim = 2048;
static constexpr int Hlay = 3;

static constexpr int BM = 128;
static constexpr int BN = 128;
static constexpr int BK = 64;               // 64 fp16 = 128B/row, padded to 144B
static constexpr int NCH = Ddim / BK;       // 32
static constexpr int GT = 256;              // 8 warps: 4(m) x 2(n), warp tile 32x64

static constexpr int ROWB = 144;            // 144 % 128 != 0, 9 coprime 8 -> conflict-free
static constexpr int TILEB = 128 * ROWB;    // 18432 per tile
static constexpr int STAGEB = 3 * TILEB;    // A_hi, A_lo, W = 55296
static constexpr int NSTAGE = 2;
static constexpr int SMEM_TOTAL = NSTAGE * STAGEB;  // 110592 -> 2 CTAs/SM

__device__ __half g_w[(size_t)Hlay * Ddim * Ddim];
__device__ __half g_act_hi[2][(size_t)Bdim * Ddim];
__device__ __half g_act_lo[2][(size_t)Bdim * Ddim];
__device__ float g_bias[Hlay * Ddim];
__device__ float g_wo[Ddim];
__device__ float g_bo;

DEV uint32_t smem_u32(const void* p) { return (uint32_t)__cvta_generic_to_shared(p); }

DEV void cp16(uint32_t s, const void* g) {
    asm volatile("cp.async.cg.shared.global [%0], [%1], 16;\n"
                 :: "r"(s), "l"(__cvta_generic_to_global(g)) : "memory");
}

DEV void ldsm4(uint32_t* r, uint32_t addr) {
    asm volatile("ldmatrix.sync.aligned.m8n8.x4.shared.b16 {%0,%1,%2,%3}, [%4];"
                 : "=r"(r[0]), "=r"(r[1]), "=r"(r[2]), "=r"(r[3]) : "r"(addr));
}

DEV void mma_f16(float* c, const uint32_t* a, const uint32_t* b) {
    asm volatile(
        "mma.sync.aligned.m16n8k16.row.col.f32.f16.f16.f32 "
        "{%0,%1,%2,%3}, {%4,%5,%6,%7}, {%8,%9}, {%0,%1,%2,%3};\n"
        : "+f"(c[0]), "+f"(c[1]), "+f"(c[2]), "+f"(c[3])
        : "r"(a[0]), "r"(a[1]), "r"(a[2]), "r"(a[3]), "r"(b[0]), "r"(b[1]));
}

DEV float softplusf(float x) { return fmaxf(x, 0.0f) + log1pf(expf(-fabsf(x))); }

DEV void split_pack_h(float a, float b, uint32_t& hi, uint32_t& lo) {
    __half ha = __float2half_rn(a), hb = __float2half_rn(b);
    float ra = a - __half2float(ha), rb = b - __half2float(hb);
    __half la = __float2half_rn(ra), lb = __float2half_rn(rb);
    hi = (uint32_t)__half_as_ushort(ha) | ((uint32_t)__half_as_ushort(hb) << 16);
    lo = (uint32_t)__half_as_ushort(la) | ((uint32_t)__half_as_ushort(lb) << 16);
}

// ---------------- prep ----------------
__global__ void prep_w_kernel(const float4* __restrict__ mu, const float4* __restrict__ rho,
                              const float4* __restrict__ eps) {
    const size_t n4 = (size_t)Hlay * Ddim * Ddim / 4;
    for (size_t i = (size_t)blockIdx.x * blockDim.x + threadIdx.x; i < n4;
         i += (size_t)gridDim.x * blockDim.x) {
        float4 m = mu[i], r = rho[i], e = eps[i];
        float w0 = fmaf(e.x, softplusf(r.x), m.x);
        float w1 = fmaf(e.y, softplusf(r.y), m.y);
        float w2 = fmaf(e.z, softplusf(r.z), m.z);
        float w3 = fmaf(e.w, softplusf(r.w), m.w);
        uint32_t p0 = (uint32_t)__half_as_ushort(__float2half_rn(w0))
                    | ((uint32_t)__half_as_ushort(__float2half_rn(w1)) << 16);
        uint32_t p1 = (uint32_t)__half_as_ushort(__float2half_rn(w2))
                    | ((uint32_t)__half_as_ushort(__float2half_rn(w3)) << 16);
        *reinterpret_cast<uint2*>(g_w + i * 4) = make_uint2(p0, p1);
    }
}

__global__ void prep_x_kernel(const float4* __restrict__ x) {
    const size_t n4 = (size_t)Bdim * Ddim / 4;
    for (size_t i = (size_t)blockIdx.x * blockDim.x + threadIdx.x; i < n4;
         i += (size_t)gridDim.x * blockDim.x) {
        float4 v = x[i];
        uint32_t h0, l0, h1, l1;
        split_pack_h(v.x, v.y, h0, l0);
        split_pack_h(v.z, v.w, h1, l1);
        *reinterpret_cast<uint2*>(&g_act_hi[0][i * 4]) = make_uint2(h0, h1);
        *reinterpret_cast<uint2*>(&g_act_lo[0][i * 4]) = make_uint2(l0, l1);
    }
}

__global__ void prep_small_kernel(const float* __restrict__ bmu, const float* __restrict__ brho,
                                  const float* __restrict__ ebh,
                                  const float* __restrict__ wmo, const float* __restrict__ wro,
                                  const float* __restrict__ ewo,
                                  const float* __restrict__ bmo, const float* __restrict__ bro,
                                  const float* __restrict__ ebo) {
    int i = blockIdx.x * blockDim.x + threadIdx.x;
    if (i < Hlay * Ddim) {
        g_bias[i] = fmaf(ebh[i], softplusf(brho[i]), bmu[i]);
    } else if (i < Hlay * Ddim + Ddim) {
        int j = i - Hlay * Ddim;
        g_wo[j] = fmaf(ewo[j], softplusf(wro[j]), wmo[j]);
    } else if (i == Hlay * Ddim + Ddim) {
        g_bo = fmaf(ebo[0], softplusf(bro[0]), bmo[0]);
    }
}

// ---------------- GEMM: C = relu(A @ W^T + b), fp16 2-term split ----------------
__global__ void __launch_bounds__(GT, 2)
gemm_kernel(int layer, int inbuf, int outbuf) {
    extern __shared__ char smraw[];
    const uint32_t sb = smem_u32(smraw);
    const int tid = threadIdx.x;
    const int lane = tid & 31, w = tid >> 5;
    const int wm = w & 3, wn = w >> 2;          // warp tile: 32 (m) x 64 (n)
    const int m0 = blockIdx.x * BM, n0 = blockIdx.y * BN;

    const __half* __restrict__ a_hi = g_act_hi[inbuf];
    const __half* __restrict__ a_lo = g_act_lo[inbuf];
    const __half* __restrict__ wgt = g_w + (size_t)layer * Ddim * Ddim;
    const float* __restrict__ bias = g_bias + layer * Ddim;
    __half* __restrict__ o_hi = g_act_hi[outbuf];
    __half* __restrict__ o_lo = g_act_lo[outbuf];

    // loads: 256 thr; per tile each thread covers one 64B row-half (4 x 16B)
    const int lrow = tid >> 1, lhalf = tid & 1;
    const uint32_t lso = (uint32_t)(lrow * ROWB + lhalf * 64);

    auto load_stage = [&](int slot, int kc) {
        const uint32_t st = sb + slot * STAGEB;
        const size_t ga = (size_t)(m0 + lrow) * Ddim + kc * BK + lhalf * 32;
        const size_t gb = (size_t)(n0 + lrow) * Ddim + kc * BK + lhalf * 32;
#pragma unroll
        for (int j = 0; j < 4; j++) {
            cp16(st + lso + j * 16, a_hi + ga + j * 8);
            cp16(st + TILEB + lso + j * 16, a_lo + ga + j * 8);
            cp16(st + 2 * TILEB + lso + j * 16, wgt + gb + j * 8);
        }
        asm volatile("cp.async.commit_group;" ::: "memory");
    };

    float acc[2][8][4];
#pragma unroll
    for (int mt = 0; mt < 2; mt++)
#pragma unroll
        for (int nt = 0; nt < 8; nt++)
#pragma unroll
            for (int j = 0; j < 4; j++) acc[mt][nt][j] = 0.0f;

    const uint32_t aoff = (uint32_t)((lane & 15) * ROWB + (lane >> 4) * 16);
    const uint32_t boff = (uint32_t)((((lane & 7) + ((lane >> 4) << 3)) * ROWB)
                                     + (((lane >> 3) & 1) * 16));

    load_stage(0, 0);

    for (int kc = 0; kc < NCH; kc++) {
        const int s = kc & 1;
        asm volatile("cp.async.wait_group 0;" ::: "memory");
        __syncthreads();
        if (kc + 1 < NCH) load_stage(s ^ 1, kc + 1);

        const uint32_t st = sb + s * STAGEB;
        const uint32_t ab = st + (uint32_t)(wm * 32 * ROWB) + aoff;
        const uint32_t bb = st + 2 * TILEB + (uint32_t)(wn * 64 * ROWB) + boff;
#pragma unroll
        for (int ks = 0; ks < 4; ks++) {
            uint32_t ah[2][4], al[2][4];
#pragma unroll
            for (int mt = 0; mt < 2; mt++) {
                uint32_t a = ab + mt * 16 * ROWB + ks * 32;
                ldsm4(ah[mt], a);
                ldsm4(al[mt], a + TILEB);
            }
#pragma unroll
            for (int np = 0; np < 4; np++) {
                uint32_t bh[4];
                ldsm4(bh, bb + np * 16 * ROWB + ks * 32);
#pragma unroll
                for (int mt = 0; mt < 2; mt++)
#pragma unroll
                    for (int hf = 0; hf < 2; hf++) {
                        float* c = acc[mt][np * 2 + hf];
                        mma_f16(c, ah[mt], &bh[2 * hf]);
                        mma_f16(c, al[mt], &bh[2 * hf]);
                    }
            }
        }
    }

    // epilogue: bias + relu + fp16 hi/lo split
    const int mrow = m0 + wm * 32 + (lane >> 2);
    const int ncol0 = n0 + wn * 64 + 2 * (lane & 3);
#pragma unroll
    for (int mt = 0; mt < 2; mt++) {
#pragma unroll
        for (int nt = 0; nt < 8; nt++) {
            const int n = ncol0 + nt * 8;
            const float b0 = __ldg(bias + n), b1 = __ldg(bias + n + 1);
#pragma unroll
            for (int hf = 0; hf < 2; hf++) {
                const int m = mrow + mt * 16 + hf * 8;
                float y0 = fmaxf(acc[mt][nt][2 * hf] + b0, 0.0f);
                float y1 = fmaxf(acc[mt][nt][2 * hf + 1] + b1, 0.0f);
                uint32_t hi, lo;
                split_pack_h(y0, y1, hi, lo);
                *reinterpret_cast<uint32_t*>(o_hi + (size_t)m * Ddim + n) = hi;
                *reinterpret_cast<uint32_t*>(o_lo + (size_t)m * Ddim + n) = lo;
            }
        }
    }
}

// ---------------- output layer: N=1 dot ----------------
__global__ void out_kernel(float* __restrict__ out) {
    const int row = blockIdx.x * 8 + (threadIdx.x >> 5);
    const int lid = threadIdx.x & 31;
    const __half* hi = g_act_hi[1] + (size_t)row * Ddim;
    const __half* lo = g_act_lo[1] + (size_t)row * Ddim;
    float s = 0.0f;
    for (int j = lid; j < Ddim; j += 32)
        s += (__half2float(__ldg(hi + j)) + __half2float(__ldg(lo + j))) * __ldg(&g_wo[j]);
#pragma unroll
    for (int o = 16; o; o >>= 1) s += __shfl_xor_sync(0xFFFFFFFFu, s, o);
    if (lid == 0) out[row] = s + g_bo;
}

extern "C" void kernel_launch(void* const* d_in, const int* in_sizes, int n_in,
                              void* d_out, int out_size) {
    (void)in_sizes; (void)n_in; (void)out_size;
    prep_w_kernel<<<4096, 256>>>((const float4*)d_in[1], (const float4*)d_in[2],
                                 (const float4*)d_in[9]);
    prep_x_kernel<<<2048, 256>>>((const float4*)d_in[0]);
    prep_small_kernel<<<33, 256>>>((const float*)d_in[3], (const float*)d_in[4],
                                   (const float*)d_in[10],
                                   (const float*)d_in[5], (const float*)d_in[6],
                                   (const float*)d_in[11],
                                   (const float*)d_in[7], (const float*)d_in[8],
                                   (const float*)d_in[12]);
    cudaFuncSetAttribute(gemm_kernel, cudaFuncAttributeMaxDynamicSharedMemorySize, SMEM_TOTAL);
    dim3 grid(Bdim / BM, Ddim / BN);
    gemm_kernel<<<grid, GT, SMEM_TOTAL>>>(0, 0, 1);
    gemm_kernel<<<grid, GT, SMEM_TOTAL>>>(1, 1, 0);
    gemm_kernel<<<grid, GT, SMEM_TOTAL>>>(2, 0, 1);
    out_kernel<<<Bdim / 8, 256>>>((float*)d_out);
}

// round 8
// speedup vs baseline: 1.6885x; 1.6885x over previous
#include <cuda_runtime.h>
#include <cuda_bf16.h>
#include <cuda_fp16.h>
#include <cstdint>
#include <cstddef>

#define DEV __device__ __forceinline__

static constexpr int Bdim = 4096;
static constexpr int Ddim = 2048;
static constexpr int Hlay = 3;

static constexpr int BM = 128;
static constexpr int BN = 128;
static constexpr int BK = 32;               // 32 fp16 = 64B/row, padded to 80B
static constexpr int NCH = Ddim / BK;       // 64
static constexpr int GT = 256;              // 8 warps: 4(m) x 2(n), warp tile 32x64

static constexpr int ROWB = 80;             // padded row bytes (conflict-free ldmatrix)
static constexpr int TILEB = 128 * ROWB;    // 10240 per tile
static constexpr int STAGEB = 3 * TILEB;    // A_hi, A_lo, W = 30720
static constexpr int NSTAGE = 3;
static constexpr int SMEM_TOTAL = NSTAGE * STAGEB;  // 92160 -> 2 CTAs/SM

__device__ __half g_w[(size_t)Hlay * Ddim * Ddim];
__device__ __half g_act_hi[2][(size_t)Bdim * Ddim];
__device__ __half g_act_lo[2][(size_t)Bdim * Ddim];
__device__ float g_bias[Hlay * Ddim];
__device__ float g_wo[Ddim];
__device__ float g_bo;

DEV uint32_t smem_u32(const void* p) { return (uint32_t)__cvta_generic_to_shared(p); }

DEV void cp16(uint32_t s, const void* g) {
    asm volatile("cp.async.cg.shared.global [%0], [%1], 16;\n"
                 :: "r"(s), "l"(__cvta_generic_to_global(g)) : "memory");
}

DEV void ldsm4(uint32_t* r, uint32_t addr) {
    asm volatile("ldmatrix.sync.aligned.m8n8.x4.shared.b16 {%0,%1,%2,%3}, [%4];"
                 : "=r"(r[0]), "=r"(r[1]), "=r"(r[2]), "=r"(r[3]) : "r"(addr));
}

DEV void mma_f16(float* c, const uint32_t* a, const uint32_t* b) {
    asm volatile(
        "mma.sync.aligned.m16n8k16.row.col.f32.f16.f16.f32 "
        "{%0,%1,%2,%3}, {%4,%5,%6,%7}, {%8,%9}, {%0,%1,%2,%3};\n"
        : "+f"(c[0]), "+f"(c[1]), "+f"(c[2]), "+f"(c[3])
        : "r"(a[0]), "r"(a[1]), "r"(a[2]), "r"(a[3]), "r"(b[0]), "r"(b[1]));
}

DEV float softplusf(float x) { return fmaxf(x, 0.0f) + log1pf(expf(-fabsf(x))); }

DEV void split_pack_h(float a, float b, uint32_t& hi, uint32_t& lo) {
    __half ha = __float2half_rn(a), hb = __float2half_rn(b);
    float ra = a - __half2float(ha), rb = b - __half2float(hb);
    __half la = __float2half_rn(ra), lb = __float2half_rn(rb);
    hi = (uint32_t)__half_as_ushort(ha) | ((uint32_t)__half_as_ushort(hb) << 16);
    lo = (uint32_t)__half_as_ushort(la) | ((uint32_t)__half_as_ushort(lb) << 16);
}

// ---------------- prep ----------------
__global__ void prep_w_kernel(const float4* __restrict__ mu, const float4* __restrict__ rho,
                              const float4* __restrict__ eps) {
    const size_t n4 = (size_t)Hlay * Ddim * Ddim / 4;
    for (size_t i = (size_t)blockIdx.x * blockDim.x + threadIdx.x; i < n4;
         i += (size_t)gridDim.x * blockDim.x) {
        float4 m = mu[i], r = rho[i], e = eps[i];
        float w0 = fmaf(e.x, softplusf(r.x), m.x);
        float w1 = fmaf(e.y, softplusf(r.y), m.y);
        float w2 = fmaf(e.z, softplusf(r.z), m.z);
        float w3 = fmaf(e.w, softplusf(r.w), m.w);
        uint32_t p0 = (uint32_t)__half_as_ushort(__float2half_rn(w0))
                    | ((uint32_t)__half_as_ushort(__float2half_rn(w1)) << 16);
        uint32_t p1 = (uint32_t)__half_as_ushort(__float2half_rn(w2))
                    | ((uint32_t)__half_as_ushort(__float2half_rn(w3)) << 16);
        *reinterpret_cast<uint2*>(g_w + i * 4) = make_uint2(p0, p1);
    }
}

__global__ void prep_x_kernel(const float4* __restrict__ x) {
    const size_t n4 = (size_t)Bdim * Ddim / 4;
    for (size_t i = (size_t)blockIdx.x * blockDim.x + threadIdx.x; i < n4;
         i += (size_t)gridDim.x * blockDim.x) {
        float4 v = x[i];
        uint32_t h0, l0, h1, l1;
        split_pack_h(v.x, v.y, h0, l0);
        split_pack_h(v.z, v.w, h1, l1);
        *reinterpret_cast<uint2*>(&g_act_hi[0][i * 4]) = make_uint2(h0, h1);
        *reinterpret_cast<uint2*>(&g_act_lo[0][i * 4]) = make_uint2(l0, l1);
    }
}

__global__ void prep_small_kernel(const float* __restrict__ bmu, const float* __restrict__ brho,
                                  const float* __restrict__ ebh,
                                  const float* __restrict__ wmo, const float* __restrict__ wro,
                                  const float* __restrict__ ewo,
                                  const float* __restrict__ bmo, const float* __restrict__ bro,
                                  const float* __restrict__ ebo) {
    int i = blockIdx.x * blockDim.x + threadIdx.x;
    if (i < Hlay * Ddim) {
        g_bias[i] = fmaf(ebh[i], softplusf(brho[i]), bmu[i]);
    } else if (i < Hlay * Ddim + Ddim) {
        int j = i - Hlay * Ddim;
        g_wo[j] = fmaf(ewo[j], softplusf(wro[j]), wmo[j]);
    } else if (i == Hlay * Ddim + Ddim) {
        g_bo = fmaf(ebo[0], softplusf(bro[0]), bmo[0]);
    }
}

// ---------------- GEMM: C = relu(A @ W^T + b), fp16 2-term split ----------------
__global__ void __launch_bounds__(GT, 2)
gemm_kernel(int layer, int inbuf, int outbuf) {
    extern __shared__ char smraw[];
    const uint32_t sb = smem_u32(smraw);
    const int tid = threadIdx.x;
    const int lane = tid & 31, w = tid >> 5;
    const int wm = w & 3, wn = w >> 2;          // warp tile: 32 (m) x 64 (n)
    const int m0 = blockIdx.x * BM, n0 = blockIdx.y * BN;

    const __half* __restrict__ a_hi = g_act_hi[inbuf];
    const __half* __restrict__ a_lo = g_act_lo[inbuf];
    const __half* __restrict__ wgt = g_w + (size_t)layer * Ddim * Ddim;
    const float* __restrict__ bias = g_bias + layer * Ddim;
    __half* __restrict__ o_hi = g_act_hi[outbuf];
    __half* __restrict__ o_lo = g_act_lo[outbuf];

    // loads: 256 thr; per tile each thread covers 1 row-half (2 x 16B)
    const int lrow = tid >> 1, lc0 = (tid & 1) * 2;
    const uint32_t lso = (uint32_t)(lrow * ROWB + lc0 * 16);

    auto load_stage = [&](int slot, int kc) {
        const uint32_t st = sb + slot * STAGEB;
        const size_t ga = (size_t)(m0 + lrow) * Ddim + kc * BK + lc0 * 8;
        const size_t gb = (size_t)(n0 + lrow) * Ddim + kc * BK + lc0 * 8;
        cp16(st + lso, a_hi + ga);
        cp16(st + lso + 16, a_hi + ga + 8);
        cp16(st + TILEB + lso, a_lo + ga);
        cp16(st + TILEB + lso + 16, a_lo + ga + 8);
        cp16(st + 2 * TILEB + lso, wgt + gb);
        cp16(st + 2 * TILEB + lso + 16, wgt + gb + 8);
        asm volatile("cp.async.commit_group;" ::: "memory");
    };

    float acc[2][8][4];
#pragma unroll
    for (int mt = 0; mt < 2; mt++)
#pragma unroll
        for (int nt = 0; nt < 8; nt++)
#pragma unroll
            for (int j = 0; j < 4; j++) acc[mt][nt][j] = 0.0f;

    const uint32_t aoff = (uint32_t)((lane & 15) * ROWB + (lane >> 4) * 16);
    const uint32_t boff = (uint32_t)((((lane & 7) + ((lane >> 4) << 3)) * ROWB)
                                     + (((lane >> 3) & 1) * 16));

    load_stage(0, 0);
    load_stage(1, 1);

    int slot = 0;
    for (int kc = 0; kc < NCH; kc++) {
        if (kc == NCH - 1) asm volatile("cp.async.wait_group 0;" ::: "memory");
        else               asm volatile("cp.async.wait_group 1;" ::: "memory");
        __syncthreads();
        if (kc + 2 < NCH) {
            int ns = slot + 2; if (ns >= NSTAGE) ns -= NSTAGE;
            load_stage(ns, kc + 2);
        }

        const uint32_t st = sb + slot * STAGEB;
        const uint32_t ab = st + (uint32_t)(wm * 32 * ROWB) + aoff;
        const uint32_t bb = st + 2 * TILEB + (uint32_t)(wn * 64 * ROWB) + boff;

        // software-pipelined 8 micro-steps: (ks 0..1) x (np 0..3)
        uint32_t ah[2][2][4], al[2][2][4];   // [ks][mt][4]
        uint32_t bh[2][4];                   // double-buffered B fragment
        ldsm4(ah[0][0], ab);
        ldsm4(al[0][0], ab + TILEB);
        ldsm4(ah[0][1], ab + 16 * ROWB);
        ldsm4(al[0][1], ab + 16 * ROWB + TILEB);
        ldsm4(bh[0], bb);
#pragma unroll
        for (int step = 0; step < 8; step++) {
            const int ks = step >> 2, np = step & 3;
            const int cur = step & 1, nxt = cur ^ 1;
            if (step < 7) {
                const int s2 = step + 1;
                ldsm4(bh[nxt], bb + (uint32_t)((s2 & 3) * 16 * ROWB + (s2 >> 2) * 32));
            }
            if (step == 2) {   // prefetch A fragments for ks=1
                uint32_t a = ab + 32;
                ldsm4(ah[1][0], a);
                ldsm4(al[1][0], a + TILEB);
                ldsm4(ah[1][1], a + 16 * ROWB);
                ldsm4(al[1][1], a + 16 * ROWB + TILEB);
            }
#pragma unroll
            for (int mt = 0; mt < 2; mt++)
#pragma unroll
                for (int hf = 0; hf < 2; hf++) {
                    float* c = acc[mt][np * 2 + hf];
                    mma_f16(c, ah[ks][mt], &bh[cur][2 * hf]);
                    mma_f16(c, al[ks][mt], &bh[cur][2 * hf]);
                }
        }
        if (++slot >= NSTAGE) slot = 0;
    }

    // epilogue: bias + relu + fp16 hi/lo split
    const int mrow = m0 + wm * 32 + (lane >> 2);
    const int ncol0 = n0 + wn * 64 + 2 * (lane & 3);
#pragma unroll
    for (int mt = 0; mt < 2; mt++) {
#pragma unroll
        for (int nt = 0; nt < 8; nt++) {
            const int n = ncol0 + nt * 8;
            const float b0 = __ldg(bias + n), b1 = __ldg(bias + n + 1);
#pragma unroll
            for (int hf = 0; hf < 2; hf++) {
                const int m = mrow + mt * 16 + hf * 8;
                float y0 = fmaxf(acc[mt][nt][2 * hf] + b0, 0.0f);
                float y1 = fmaxf(acc[mt][nt][2 * hf + 1] + b1, 0.0f);
                uint32_t hi, lo;
                split_pack_h(y0, y1, hi, lo);
                *reinterpret_cast<uint32_t*>(o_hi + (size_t)m * Ddim + n) = hi;
                *reinterpret_cast<uint32_t*>(o_lo + (size_t)m * Ddim + n) = lo;
            }
        }
    }
}

// ---------------- output layer: N=1 dot ----------------
__global__ void out_kernel(float* __restrict__ out) {
    const int row = blockIdx.x * 8 + (threadIdx.x >> 5);
    const int lid = threadIdx.x & 31;
    const __half* hi = g_act_hi[1] + (size_t)row * Ddim;
    const __half* lo = g_act_lo[1] + (size_t)row * Ddim;
    float s = 0.0f;
    for (int j = lid; j < Ddim; j += 32)
        s += (__half2float(__ldg(hi + j)) + __half2float(__ldg(lo + j))) * __ldg(&g_wo[j]);
#pragma unroll
    for (int o = 16; o; o >>= 1) s += __shfl_xor_sync(0xFFFFFFFFu, s, o);
    if (lid == 0) out[row] = s + g_bo;
}

extern "C" void kernel_launch(void* const* d_in, const int* in_sizes, int n_in,
                              void* d_out, int out_size) {
    (void)in_sizes; (void)n_in; (void)out_size;
    prep_w_kernel<<<4096, 256>>>((const float4*)d_in[1], (const float4*)d_in[2],
                                 (const float4*)d_in[9]);
    prep_x_kernel<<<2048, 256>>>((const float4*)d_in[0]);
    prep_small_kernel<<<33, 256>>>((const float*)d_in[3], (const float*)d_in[4],
                                   (const float*)d_in[10],
                                   (const float*)d_in[5], (const float*)d_in[6],
                                   (const float*)d_in[11],
                                   (const float*)d_in[7], (const float*)d_in[8],
                                   (const float*)d_in[12]);
    cudaFuncSetAttribute(gemm_kernel, cudaFuncAttributeMaxDynamicSharedMemorySize, SMEM_TOTAL);
    dim3 grid(Bdim / BM, Ddim / BN);
    gemm_kernel<<<grid, GT, SMEM_TOTAL>>>(0, 0, 1);
    gemm_kernel<<<grid, GT, SMEM_TOTAL>>>(1, 1, 0);
    gemm_kernel<<<grid, GT, SMEM_TOTAL>>>(2, 0, 1);
    out_kernel<<<Bdim / 8, 256>>>((float*)d_out);
}